// round 2
// baseline (speedup 1.0000x reference)
#include <cuda_runtime.h>

#define S_LEN   8192
#define BATCH   8
#define DIM     128
#define NB      32            // blocks per batch (S/BS)
#define BS      256           // block size
#define HALO    255
#define WIN     766           // BS + 2*HALO
#define NROWS   (BATCH * S_LEN)   // 65536

// Scratch for projected q,k,v (static device arrays; allocation-free rule)
__device__ float g_q[NROWS * DIM];
__device__ float g_k[NROWS * DIM];
__device__ float g_v[NROWS * DIM];

__device__ __forceinline__ float f4get(const float4& v, int i) {
    return (i == 0) ? v.x : (i == 1) ? v.y : (i == 2) ? v.z : v.w;
}

// ---------------------------------------------------------------------------
// Phase 1: q/k/v = x @ W^T + b.   One matrix per blockIdx.y.
// CTA: 256 threads, tile 128 rows x 128 cols, 8x8 micro per thread.
// smem: w_s [128][132] (full W, padded), x_s [128][36] (32-d chunk, padded)
// ---------------------------------------------------------------------------
#define P1_SMEM ((128 * 132 + 128 * 36) * 4)   // 86016 bytes

__global__ __launch_bounds__(256, 2)
void qkv_proj_kernel(const float* __restrict__ x,
                     const float* __restrict__ Wq, const float* __restrict__ bq,
                     const float* __restrict__ Wk, const float* __restrict__ bk,
                     const float* __restrict__ Wv, const float* __restrict__ bv)
{
    extern __shared__ float sm[];
    float* w_s = sm;                  // [128][132]
    float* x_s = sm + 128 * 132;      // [128][36]

    const int m = blockIdx.y;
    const float* W    = (m == 0) ? Wq : (m == 1) ? Wk : Wv;
    const float* bias = (m == 0) ? bq : (m == 1) ? bk : bv;
    float* outp       = (m == 0) ? g_q : (m == 1) ? g_k : g_v;

    const int tid = threadIdx.x;
    const int tx = tid & 15;
    const int ty = tid >> 4;
    const int r0 = blockIdx.x * 128;

    // Load full W (128x128) into smem, padded rows of 33 float4
    const float4* W4 = (const float4*)W;
    float4* w_s4 = (float4*)w_s;
#pragma unroll
    for (int i = 0; i < 16; i++) {
        int f4 = tid + 256 * i;
        int h = f4 >> 5, d4 = f4 & 31;
        w_s4[h * 33 + d4] = W4[f4];
    }

    float acc[8][8];
#pragma unroll
    for (int r = 0; r < 8; r++)
#pragma unroll
        for (int c = 0; c < 8; c++) acc[r][c] = 0.0f;

    const float4* x4g = (const float4*)x;
    float4* x_s4 = (float4*)x_s;

    for (int kk = 0; kk < 4; kk++) {
        __syncthreads();   // covers w_s on first iter, x_s reuse after
#pragma unroll
        for (int i = 0; i < 4; i++) {
            int f4 = tid + 256 * i;
            int r = f4 >> 3, d4 = f4 & 7;
            x_s4[r * 9 + d4] = x4g[(r0 + r) * 32 + kk * 8 + d4];
        }
        __syncthreads();

#pragma unroll
        for (int d4 = 0; d4 < 8; d4++) {
            float4 xv[8];
#pragma unroll
            for (int r = 0; r < 8; r++) xv[r] = x_s4[(ty * 8 + r) * 9 + d4];
#pragma unroll
            for (int c = 0; c < 8; c++) {
                float4 wv = w_s4[(c * 16 + tx) * 33 + kk * 8 + d4];
#pragma unroll
                for (int r = 0; r < 8; r++) {
                    acc[r][c] += xv[r].x * wv.x;
                    acc[r][c] += xv[r].y * wv.y;
                    acc[r][c] += xv[r].z * wv.z;
                    acc[r][c] += xv[r].w * wv.w;
                }
            }
        }
    }

    // Epilogue: add bias, store
    float bvals[8];
#pragma unroll
    for (int c = 0; c < 8; c++) bvals[c] = bias[c * 16 + tx];
#pragma unroll
    for (int r = 0; r < 8; r++) {
        int row = r0 + ty * 8 + r;
#pragma unroll
        for (int c = 0; c < 8; c++) {
            outp[row * DIM + c * 16 + tx] = acc[r][c] + bvals[c];
        }
    }
}

// ---------------------------------------------------------------------------
// Phase 2: per (batch, block):  M = K_win^T @ V_win;  out = scale * q_blk @ M
// CTA: 256 threads (16x16), one CTA per (b, n).
// smem: M_s [128][132], k_s [32][132], v_s [32][132] (q_s reuses k_s/v_s)
// ---------------------------------------------------------------------------
#define P2_SMEM ((128 * 132 + 2 * 32 * 132) * 4)   // 101376 bytes

__global__ __launch_bounds__(256, 2)
void block_attn_kernel(float* __restrict__ out)
{
    extern __shared__ float sm[];
    float* M_s = sm;                      // [128][132]
    float* k_s = sm + 128 * 132;          // [32][132]
    float* v_s = k_s + 32 * 132;          // [32][132]
    float* q_s = k_s;                     // part B reuse: [128][36] = 4608 floats <= 8448

    const int tid = threadIdx.x;
    const int tx = tid & 15;
    const int ty = tid >> 4;
    const int bn = blockIdx.x;            // b*NB + n
    const int b = bn >> 5;
    const int n = bn & 31;
    const int base = b * S_LEN;           // row base in g_k/g_v/g_q
    const int g0 = n * BS - HALO;         // first window position (may be <0)

    float acc[8][8];
#pragma unroll
    for (int r = 0; r < 8; r++)
#pragma unroll
        for (int c = 0; c < 8; c++) acc[r][c] = 0.0f;

    float4* k_s4 = (float4*)k_s;
    float4* v_s4 = (float4*)v_s;
    const float4* kg4 = (const float4*)g_k;
    const float4* vg4 = (const float4*)g_v;

    // ---- Part A: M = sum over window of k ⊗ v, streamed in chunks of 32 ----
    for (int ci = 0; ci < 24; ci++) {
        __syncthreads();
#pragma unroll
        for (int i = 0; i < 4; i++) {
            int f4 = tid + 256 * i;
            int j = f4 >> 5, d4 = f4 & 31;
            int t = ci * 32 + j;
            int g = g0 + t;
            bool ok = (t < WIN) && (g >= 0) && (g < S_LEN);
            float4 kv = make_float4(0.f, 0.f, 0.f, 0.f);
            float4 vv = make_float4(0.f, 0.f, 0.f, 0.f);
            if (ok) {
                kv = kg4[(base + g) * 32 + d4];
                vv = vg4[(base + g) * 32 + d4];
            }
            k_s4[j * 33 + d4] = kv;
            v_s4[j * 33 + d4] = vv;
        }
        __syncthreads();

#pragma unroll 4
        for (int j = 0; j < 32; j++) {
            float4 ka = k_s4[j * 33 + ty * 2];
            float4 kb = k_s4[j * 33 + ty * 2 + 1];
            float kr[8] = {ka.x, ka.y, ka.z, ka.w, kb.x, kb.y, kb.z, kb.w};
            float vc[8];
#pragma unroll
            for (int c = 0; c < 8; c++) vc[c] = v_s[j * 132 + c * 16 + tx];
#pragma unroll
            for (int r = 0; r < 8; r++)
#pragma unroll
                for (int c = 0; c < 8; c++) acc[r][c] += kr[r] * vc[c];
        }
    }

    // Store M tile to smem (rows ty*8+r, cols c*16+tx)
#pragma unroll
    for (int r = 0; r < 8; r++)
#pragma unroll
        for (int c = 0; c < 8; c++)
            M_s[(ty * 8 + r) * 132 + c * 16 + tx] = acc[r][c];

    // ---- Part B: out = scale * q_blk @ M ----
    const float scale = 0.088388347648318447f;  // 1/sqrt(128)
    const float4* qg4 = (const float4*)g_q;
    float4* q_s4 = (float4*)q_s;
    const int qrow0 = base + n * BS;

    for (int it = 0; it < 2; it++) {
        float oacc[8][8];
#pragma unroll
        for (int r = 0; r < 8; r++)
#pragma unroll
            for (int c = 0; c < 8; c++) oacc[r][c] = 0.0f;

        for (int kk = 0; kk < 4; kk++) {
            __syncthreads();   // protects k_s/v_s (part A) and prior-iter q_s reads; M_s stores precede
#pragma unroll
            for (int i = 0; i < 4; i++) {
                int f4 = tid + 256 * i;
                int r = f4 >> 3, d4 = f4 & 7;
                q_s4[r * 9 + d4] = qg4[(qrow0 + it * 128 + r) * 32 + kk * 8 + d4];
            }
            __syncthreads();

#pragma unroll
            for (int d4 = 0; d4 < 8; d4++) {
                float4 qv[8];
#pragma unroll
                for (int r = 0; r < 8; r++) qv[r] = q_s4[(ty * 8 + r) * 9 + d4];
#pragma unroll
                for (int dd = 0; dd < 4; dd++) {
                    int drow = kk * 32 + d4 * 4 + dd;
                    float mv[8];
#pragma unroll
                    for (int c = 0; c < 8; c++) mv[c] = M_s[drow * 132 + c * 16 + tx];
#pragma unroll
                    for (int r = 0; r < 8; r++) {
                        float qs = f4get(qv[r], dd);
#pragma unroll
                        for (int c = 0; c < 8; c++) oacc[r][c] += qs * mv[c];
                    }
                }
            }
        }

        // Write output block
#pragma unroll
        for (int r = 0; r < 8; r++) {
            int row = qrow0 + it * 128 + ty * 8 + r;
#pragma unroll
            for (int c = 0; c < 8; c++) {
                out[row * DIM + c * 16 + tx] = oacc[r][c] * scale;
            }
        }
    }
}

// ---------------------------------------------------------------------------
extern "C" void kernel_launch(void* const* d_in, const int* in_sizes, int n_in,
                              void* d_out, int out_size)
{
    const float* x  = (const float*)d_in[0];
    const float* Wq = (const float*)d_in[1];
    const float* bq = (const float*)d_in[2];
    const float* Wk = (const float*)d_in[3];
    const float* bk = (const float*)d_in[4];
    const float* Wv = (const float*)d_in[5];
    const float* bv = (const float*)d_in[6];
    float* out = (float*)d_out;

    cudaFuncSetAttribute(qkv_proj_kernel,
                         cudaFuncAttributeMaxDynamicSharedMemorySize, P1_SMEM);
    cudaFuncSetAttribute(block_attn_kernel,
                         cudaFuncAttributeMaxDynamicSharedMemorySize, P2_SMEM);

    qkv_proj_kernel<<<dim3(NROWS / 128, 3), 256, P1_SMEM>>>(x, Wq, bq, Wk, bk, Wv, bv);
    block_attn_kernel<<<BATCH * NB, 256, P2_SMEM>>>(out);
}

// round 4
// speedup vs baseline: 1.3674x; 1.3674x over previous
#include <cuda_runtime.h>
#include <cuda_bf16.h>
#include <cstdint>

#define S_LEN 8192
#define NBATCH 8
#define DIM 128
#define NB 32
#define NROWS (NBATCH*S_LEN)
#define LDB 136          // bf16 elements per operand smem row (272 B, conflict-free)
#define LDS 132          // f32 elements per staging row

// ---------------- scratch (static device arrays; allocation-free rule) -----
__device__ __align__(16) __nv_bfloat16 g_q_hi[(size_t)NROWS*DIM];
__device__ __align__(16) __nv_bfloat16 g_q_lo[(size_t)NROWS*DIM];
__device__ __align__(16) __nv_bfloat16 g_k_hi[(size_t)NBATCH*DIM*S_LEN]; // [b][h][t]
__device__ __align__(16) __nv_bfloat16 g_k_lo[(size_t)NBATCH*DIM*S_LEN];
__device__ __align__(16) __nv_bfloat16 g_v_hi[(size_t)NBATCH*DIM*S_LEN];
__device__ __align__(16) __nv_bfloat16 g_v_lo[(size_t)NBATCH*DIM*S_LEN];
__device__ __align__(16) float g_C[(size_t)NBATCH*NB*DIM*DIM];           // C'[hv][hk]

// smem byte offsets
#define O_AH 0
#define O_AL 34816
#define O_BH 69632
#define O_BL 104448
#define O_EXT 139264             // K1: bias f32[128];  K3: edge/dot arrays
#define O_KE0 (O_EXT)
#define O_VE0 (O_EXT+512)
#define O_KE1 (O_EXT+1024)
#define O_VE1 (O_EXT+1536)
#define O_DL  (O_EXT+2048)
#define O_DR  (O_EXT+2560)
#define SMEM_ALL (O_EXT+3072)    // 142336 bytes
// staging overlays A region (67584 <= 69632)

__device__ __forceinline__ unsigned smem_u32(const void* p){
    unsigned a; asm("{ .reg .u64 t; cvta.to.shared.u64 t, %1; cvt.u32.u64 %0, t; }":"=r"(a):"l"(p)); return a;
}
__device__ __forceinline__ void ldm4(unsigned* r, unsigned addr){
    asm volatile("ldmatrix.sync.aligned.m8n8.x4.shared.b16 {%0,%1,%2,%3}, [%4];"
        : "=r"(r[0]),"=r"(r[1]),"=r"(r[2]),"=r"(r[3]) : "r"(addr));
}
__device__ __forceinline__ void mma16816(float* d, const unsigned* a, unsigned b0, unsigned b1){
    asm volatile("mma.sync.aligned.m16n8k16.row.col.f32.bf16.bf16.f32 "
        "{%0,%1,%2,%3}, {%4,%5,%6,%7}, {%8,%9}, {%0,%1,%2,%3};"
        : "+f"(d[0]),"+f"(d[1]),"+f"(d[2]),"+f"(d[3])
        : "r"(a[0]),"r"(a[1]),"r"(a[2]),"r"(a[3]), "r"(b0),"r"(b1));
}

// One K=128 pass: D(128x128) += A(128xK) * B(128xK)^T, operands bf16 in smem.
__device__ __forceinline__ void warp_pass(unsigned aB, unsigned bB,
                                          float acc[2][8][4], int wr, int wc, int lane){
    unsigned aAddr = aB + (unsigned)((wr*32 + (lane&15))*272) + ((lane>>4)<<4);
    unsigned bAddr = bB + (unsigned)((wc*64 + (lane&7) + ((lane>>4)<<3))*272) + (((lane>>3)&1)<<4);
#pragma unroll
    for(int ks=0; ks<8; ks++){
        unsigned a0[4], a1[4], br[4][4];
        ldm4(a0, aAddr + ks*32);
        ldm4(a1, aAddr + 16*272 + ks*32);
#pragma unroll
        for(int n2=0; n2<4; n2++) ldm4(br[n2], bAddr + n2*16*272 + ks*32);
#pragma unroll
        for(int nt=0; nt<8; nt++){
            unsigned b0 = br[nt>>1][(nt&1)*2], b1 = br[nt>>1][(nt&1)*2+1];
            mma16816(acc[0][nt], a0, b0, b1);
            mma16816(acc[1][nt], a1, b0, b1);
        }
    }
}
__device__ __forceinline__ void mma3(unsigned sb, float acc[2][8][4], int wr, int wc, int lane){
    warp_pass(sb+O_AH, sb+O_BH, acc, wr, wc, lane);
    warp_pass(sb+O_AH, sb+O_BL, acc, wr, wc, lane);
    warp_pass(sb+O_AL, sb+O_BH, acc, wr, wc, lane);
}
__device__ __forceinline__ void stage_acc(float* stag, float acc[2][8][4], int wr, int wc, int lane){
    int rb = wr*32 + (lane>>2), cb = wc*64 + (lane&3)*2;
#pragma unroll
    for(int mt=0; mt<2; mt++)
#pragma unroll
    for(int nt=0; nt<8; nt++){
        int r = rb + mt*16, c = cb + nt*8;
        *(float2*)&stag[r*LDS+c]     = make_float2(acc[mt][nt][0], acc[mt][nt][1]);
        *(float2*)&stag[(r+8)*LDS+c] = make_float2(acc[mt][nt][2], acc[mt][nt][3]);
    }
}
// 64 f32 -> hi/lo bf16 (contiguous)
__device__ __forceinline__ void cvt64(const float* s, __nv_bfloat16* dh, __nv_bfloat16* dl){
#pragma unroll
    for(int g=0; g<8; g++){
        float4 a=((const float4*)s)[2*g], b=((const float4*)s)[2*g+1];
        float f[8]={a.x,a.y,a.z,a.w,b.x,b.y,b.z,b.w};
        __align__(16) __nv_bfloat16 h[8], l[8];
#pragma unroll
        for(int i=0;i<8;i++){ h[i]=__float2bfloat16_rn(f[i]); l[i]=__float2bfloat16_rn(f[i]-__bfloat162float(h[i])); }
        ((uint4*)dh)[g]=*(const uint4*)h; ((uint4*)dl)[g]=*(const uint4*)l;
    }
}
__device__ __forceinline__ void cpy64(const __nv_bfloat16* s, __nv_bfloat16* d){
#pragma unroll
    for(int g=0; g<8; g++) ((uint4*)d)[g]=((const uint4*)s)[g];
}

// ============== K1: qkv projection ==========================================
__global__ __launch_bounds__(256,1) void k1(const float* __restrict__ x,
    const float* __restrict__ Wq, const float* __restrict__ bq,
    const float* __restrict__ Wk, const float* __restrict__ bk,
    const float* __restrict__ Wv, const float* __restrict__ bv)
{
    extern __shared__ char sm[];
    unsigned sb = smem_u32(sm);
    const int tid=threadIdx.x, lane=tid&31, warp=tid>>5, wr=warp>>1, wc=warp&1;
    const int m=blockIdx.y, r0=blockIdx.x*128;
    const float* W    = m==0?Wq:(m==1?Wk:Wv);
    const float* bias = m==0?bq:(m==1?bk:bv);
    __nv_bfloat16* Ah=(__nv_bfloat16*)(sm+O_AH); __nv_bfloat16* Al=(__nv_bfloat16*)(sm+O_AL);
    __nv_bfloat16* Bh=(__nv_bfloat16*)(sm+O_BH); __nv_bfloat16* Bl=(__nv_bfloat16*)(sm+O_BL);
    float* bias_s=(float*)(sm+O_EXT);
    const int r=tid>>1, hf=tid&1;
    cvt64(x + (size_t)(r0+r)*128 + hf*64, Ah + r*LDB + hf*64, Al + r*LDB + hf*64);
    cvt64(W + (size_t)r*128 + hf*64,      Bh + r*LDB + hf*64, Bl + r*LDB + hf*64);
    if(tid<128) bias_s[tid]=bias[tid];
    __syncthreads();
    float acc[2][8][4];
#pragma unroll
    for(int a=0;a<2;a++)
#pragma unroll
    for(int b=0;b<8;b++){acc[a][b][0]=acc[a][b][1]=acc[a][b][2]=acc[a][b][3]=0.f;}
    mma3(sb, acc, wr, wc, lane);
    __syncthreads();
    float* stag=(float*)(sm+O_AH);
    stage_acc(stag, acc, wr, wc, lane);
    __syncthreads();
    if(m==0){
#pragma unroll
        for(int g=0; g<8; g++){
            __align__(16) __nv_bfloat16 h[8], l[8];
#pragma unroll
            for(int i=0;i<8;i++){
                float v = stag[r*LDS + hf*64 + g*8 + i] + bias_s[hf*64+g*8+i];
                h[i]=__float2bfloat16_rn(v); l[i]=__float2bfloat16_rn(v-__bfloat162float(h[i]));
            }
            size_t off=(size_t)(r0+r)*128 + hf*64 + g*8;
            *(uint4*)(g_q_hi+off)=*(const uint4*)h; *(uint4*)(g_q_lo+off)=*(const uint4*)l;
        }
    } else {
        const int h_=r, tp=hf, bb=r0>>13, tl0=r0&8191;
        const float bsv=bias_s[h_];
        __nv_bfloat16* dh=(m==1?g_k_hi:g_v_hi)+(size_t)(bb*128+h_)*S_LEN+tl0+tp*64;
        __nv_bfloat16* dl=(m==1?g_k_lo:g_v_lo)+(size_t)(bb*128+h_)*S_LEN+tl0+tp*64;
#pragma unroll
        for(int tg=0; tg<8; tg++){
            __align__(16) __nv_bfloat16 h[8], l[8];
#pragma unroll
            for(int i=0;i<8;i++){
                float v = stag[(tp*64+tg*8+i)*LDS + h_] + bsv;
                h[i]=__float2bfloat16_rn(v); l[i]=__float2bfloat16_rn(v-__bfloat162float(h[i]));
            }
            *(uint4*)(dh+tg*8)=*(const uint4*)h; *(uint4*)(dl+tg*8)=*(const uint4*)l;
        }
    }
}

// ============== K2: C'_m[hv][hk] = sum_{t in chunk} v*k ====================
__global__ __launch_bounds__(256,1) void k2()
{
    extern __shared__ char sm[];
    unsigned sb=smem_u32(sm);
    const int tid=threadIdx.x, lane=tid&31, warp=tid>>5, wr=warp>>1, wc=warp&1;
    const int bm=blockIdx.x, b=bm>>5, mc=bm&31;
    __nv_bfloat16* Ah=(__nv_bfloat16*)(sm+O_AH); __nv_bfloat16* Al=(__nv_bfloat16*)(sm+O_AL);
    __nv_bfloat16* Bh=(__nv_bfloat16*)(sm+O_BH); __nv_bfloat16* Bl=(__nv_bfloat16*)(sm+O_BL);
    const int r=tid>>1, hf=tid&1;
    float acc[2][8][4];
#pragma unroll
    for(int a=0;a<2;a++)
#pragma unroll
    for(int c=0;c<8;c++){acc[a][c][0]=acc[a][c][1]=acc[a][c][2]=acc[a][c][3]=0.f;}
    for(int cc=0; cc<2; cc++){
        size_t off=(size_t)(b*128+r)*S_LEN + mc*256 + cc*128 + hf*64;
        cpy64(g_v_hi+off, Ah+r*LDB+hf*64);
        cpy64(g_v_lo+off, Al+r*LDB+hf*64);
        cpy64(g_k_hi+off, Bh+r*LDB+hf*64);
        cpy64(g_k_lo+off, Bl+r*LDB+hf*64);
        __syncthreads();
        mma3(sb, acc, wr, wc, lane);
        __syncthreads();
    }
    float* stag=(float*)(sm+O_AH);
    stage_acc(stag, acc, wr, wc, lane);
    __syncthreads();
    float* dst=g_C+(size_t)(bm*128+r)*128+hf*64;
#pragma unroll
    for(int g=0; g<16; g++){
        float4 o=make_float4(stag[r*LDS+hf*64+g*4],stag[r*LDS+hf*64+g*4+1],
                             stag[r*LDS+hf*64+g*4+2],stag[r*LDS+hf*64+g*4+3]);
        ((float4*)dst)[g]=o;
    }
}

// ============== K3: out = scale*(q @ Csum^T - edges) =======================
__global__ __launch_bounds__(256,1) void k3(float* __restrict__ out)
{
    extern __shared__ char sm[];
    unsigned sb=smem_u32(sm);
    const int tid=threadIdx.x, lane=tid&31, warp=tid>>5, wr=warp>>1, wc=warp&1;
    const int idx=blockIdx.x, b=idx>>6, n=(idx>>1)&31, half=idx&1;
    const size_t qrow0=(size_t)b*S_LEN + n*256 + half*128;
    __nv_bfloat16* Ah=(__nv_bfloat16*)(sm+O_AH); __nv_bfloat16* Al=(__nv_bfloat16*)(sm+O_AL);
    __nv_bfloat16* Bh=(__nv_bfloat16*)(sm+O_BH); __nv_bfloat16* Bl=(__nv_bfloat16*)(sm+O_BL);
    float* keL=(float*)(sm+O_KE0); float* veL=(float*)(sm+O_VE0);
    float* keR=(float*)(sm+O_KE1); float* veR=(float*)(sm+O_VE1);
    float* dls=(float*)(sm+O_DL);  float* drs=(float*)(sm+O_DR);
    const int r=tid>>1, hf=tid&1;
    cpy64(g_q_hi+(qrow0+r)*128+hf*64, Ah+r*LDB+hf*64);
    cpy64(g_q_lo+(qrow0+r)*128+hf*64, Al+r*LDB+hf*64);
    { // B rows = Csum[ho=r][hk 0..127], summed over valid chunks
        const int mlo=(n>0)?n-1:0, mhi=(n<31)?n+1:31;
        float s[64];
#pragma unroll
        for(int j=0;j<64;j++) s[j]=0.f;
        for(int mm=mlo; mm<=mhi; mm++){
            const float4* p=(const float4*)(g_C+(size_t)((b*32+mm)*128+r)*128+hf*64);
#pragma unroll
            for(int g=0; g<16; g++){ float4 v=p[g]; s[g*4]+=v.x; s[g*4+1]+=v.y; s[g*4+2]+=v.z; s[g*4+3]+=v.w; }
        }
        cvt64(s, Bh+r*LDB+hf*64, Bl+r*LDB+hf*64);
    }
    if(tid<128){
        int teL=n*256-256, teR=n*256+511;
        size_t rb=(size_t)(b*128+tid)*S_LEN;
        keL[tid]=(n>0)? __bfloat162float(g_k_hi[rb+teL])+__bfloat162float(g_k_lo[rb+teL]):0.f;
        veL[tid]=(n>0)? __bfloat162float(g_v_hi[rb+teL])+__bfloat162float(g_v_lo[rb+teL]):0.f;
        keR[tid]=(n<31)? __bfloat162float(g_k_hi[rb+teR])+__bfloat162float(g_k_lo[rb+teR]):0.f;
        veR[tid]=(n<31)? __bfloat162float(g_v_hi[rb+teR])+__bfloat162float(g_v_lo[rb+teR]):0.f;
    }
    __syncthreads();
    float acc[2][8][4];
#pragma unroll
    for(int a=0;a<2;a++)
#pragma unroll
    for(int c=0;c<8;c++){acc[a][c][0]=acc[a][c][1]=acc[a][c][2]=acc[a][c][3]=0.f;}
    mma3(sb, acc, wr, wc, lane);
    __syncthreads();
    if(tid<128){   // per-row edge dots from smem q (still intact)
        float dl=0.f, dr=0.f;
#pragma unroll 16
        for(int c=0; c<128; c++){
            float q=__bfloat162float(Ah[tid*LDB+c])+__bfloat162float(Al[tid*LDB+c]);
            dl+=q*keL[c]; dr+=q*keR[c];
        }
        dls[tid]=dl; drs[tid]=dr;
    }
    __syncthreads();
    float* stag=(float*)(sm+O_AH);
    stage_acc(stag, acc, wr, wc, lane);
    __syncthreads();
    const float scale=0.08838834764831845f;
    const float dlv=dls[r], drv=drs[r];
    float* op=out+(qrow0+r)*128+hf*64;
#pragma unroll
    for(int g=0; g<16; g++){
        int c0=hf*64+g*4;
        float4 o;
        o.x=scale*(stag[r*LDS+c0+0]-dlv*veL[c0+0]-drv*veR[c0+0]);
        o.y=scale*(stag[r*LDS+c0+1]-dlv*veL[c0+1]-drv*veR[c0+1]);
        o.z=scale*(stag[r*LDS+c0+2]-dlv*veL[c0+2]-drv*veR[c0+2]);
        o.w=scale*(stag[r*LDS+c0+3]-dlv*veL[c0+3]-drv*veR[c0+3]);
        ((float4*)op)[g]=o;
    }
}

// ---------------------------------------------------------------------------
extern "C" void kernel_launch(void* const* d_in, const int* in_sizes, int n_in,
                              void* d_out, int out_size)
{
    const float* x =(const float*)d_in[0];
    const float* Wq=(const float*)d_in[1]; const float* bq=(const float*)d_in[2];
    const float* Wk=(const float*)d_in[3]; const float* bk=(const float*)d_in[4];
    const float* Wv=(const float*)d_in[5]; const float* bv=(const float*)d_in[6];
    float* out=(float*)d_out;
    cudaFuncSetAttribute(k1, cudaFuncAttributeMaxDynamicSharedMemorySize, SMEM_ALL);
    cudaFuncSetAttribute(k2, cudaFuncAttributeMaxDynamicSharedMemorySize, SMEM_ALL);
    cudaFuncSetAttribute(k3, cudaFuncAttributeMaxDynamicSharedMemorySize, SMEM_ALL);
    k1<<<dim3(NROWS/128,3),256,SMEM_ALL>>>(x,Wq,bq,Wk,bk,Wv,bv);
    k2<<<NBATCH*NB,256,SMEM_ALL>>>();
    k3<<<NBATCH*NB*2,256,SMEM_ALL>>>(out);
}

// round 5
// speedup vs baseline: 1.6483x; 1.2055x over previous
#include <cuda_runtime.h>
#include <cuda_bf16.h>
#include <cstdint>

#define S_LEN 8192
#define NBATCH 8
#define DIM 128
#define NB 32
#define NROWS (NBATCH*S_LEN)
#define LDBE 136         // bf16 elems per 272B operand row
#define LDS 132          // f32 staging row

// ---------------- scratch (static device arrays; allocation-free rule) -----
__device__ __align__(16) __nv_bfloat16 g_q_hi[(size_t)NROWS*DIM];
__device__ __align__(16) __nv_bfloat16 g_q_lo[(size_t)NROWS*DIM];
__device__ __align__(16) __nv_bfloat16 g_k_hi[(size_t)NBATCH*DIM*S_LEN]; // [b][h][t]
__device__ __align__(16) __nv_bfloat16 g_k_lo[(size_t)NBATCH*DIM*S_LEN];
__device__ __align__(16) __nv_bfloat16 g_v_hi[(size_t)NBATCH*DIM*S_LEN];
__device__ __align__(16) __nv_bfloat16 g_v_lo[(size_t)NBATCH*DIM*S_LEN];
__device__ __align__(16) float g_C[(size_t)NBATCH*NB*DIM*DIM];           // C'[hv][hk]
__device__ __align__(16) __nv_bfloat16 g_w_hi[3*DIM*DIM];
__device__ __align__(16) __nv_bfloat16 g_w_lo[3*DIM*DIM];

// ---------------- helpers ---------------------------------------------------
__device__ __forceinline__ unsigned smem_u32(const void* p){
    unsigned a; asm("{ .reg .u64 t; cvta.to.shared.u64 t, %1; cvt.u32.u64 %0, t; }":"=r"(a):"l"(p)); return a;
}
__device__ __forceinline__ void ldm4(unsigned* r, unsigned addr){
    asm volatile("ldmatrix.sync.aligned.m8n8.x4.shared.b16 {%0,%1,%2,%3}, [%4];"
        : "=r"(r[0]),"=r"(r[1]),"=r"(r[2]),"=r"(r[3]) : "r"(addr));
}
__device__ __forceinline__ void mma16816(float* d, const unsigned* a, unsigned b0, unsigned b1){
    asm volatile("mma.sync.aligned.m16n8k16.row.col.f32.bf16.bf16.f32 "
        "{%0,%1,%2,%3}, {%4,%5,%6,%7}, {%8,%9}, {%0,%1,%2,%3};"
        : "+f"(d[0]),"+f"(d[1]),"+f"(d[2]),"+f"(d[3])
        : "r"(a[0]),"r"(a[1]),"r"(a[2]),"r"(a[3]), "r"(b0),"r"(b1));
}
__device__ __forceinline__ void cpa(unsigned d, const void* s){
    asm volatile("cp.async.cg.shared.global [%0], [%1], 16;"::"r"(d),"l"(s));
}
#define CPC() asm volatile("cp.async.commit_group;":::"memory")
#define CPW(n) asm volatile("cp.async.wait_group %0;"::"n"(n):"memory")

template<int LD, int KS>
__device__ __forceinline__ void warp_pass(unsigned aB, unsigned bB,
                                          float acc[2][8][4], int wr, int wc, int lane){
    unsigned aAddr = aB + (unsigned)((wr*32 + (lane&15))*LD) + ((lane>>4)<<4);
    unsigned bAddr = bB + (unsigned)((wc*64 + (lane&7) + ((lane>>4)<<3))*LD) + (((lane>>3)&1)<<4);
#pragma unroll
    for(int ks=0; ks<KS; ks++){
        unsigned a0[4], a1[4], br[4][4];
        ldm4(a0, aAddr + ks*32);
        ldm4(a1, aAddr + 16*LD + ks*32);
#pragma unroll
        for(int n2=0; n2<4; n2++) ldm4(br[n2], bAddr + n2*16*LD + ks*32);
#pragma unroll
        for(int nt=0; nt<8; nt++){
            unsigned b0 = br[nt>>1][(nt&1)*2], b1 = br[nt>>1][(nt&1)*2+1];
            mma16816(acc[0][nt], a0, b0, b1);
            mma16816(acc[1][nt], a1, b0, b1);
        }
    }
}
__device__ __forceinline__ void zacc(float acc[2][8][4]){
#pragma unroll
    for(int a=0;a<2;a++)
#pragma unroll
    for(int b=0;b<8;b++){acc[a][b][0]=acc[a][b][1]=acc[a][b][2]=acc[a][b][3]=0.f;}
}
__device__ __forceinline__ void stage_acc(float* stag, float acc[2][8][4], int wr, int wc, int lane){
    int rb = wr*32 + (lane>>2), cb = wc*64 + (lane&3)*2;
#pragma unroll
    for(int mt=0; mt<2; mt++)
#pragma unroll
    for(int nt=0; nt<8; nt++){
        int r = rb + mt*16, c = cb + nt*8;
        *(float2*)&stag[r*LDS+c]     = make_float2(acc[mt][nt][0], acc[mt][nt][1]);
        *(float2*)&stag[(r+8)*LDS+c] = make_float2(acc[mt][nt][2], acc[mt][nt][3]);
    }
}
__device__ __forceinline__ void cvt64(const float* s, __nv_bfloat16* dh, __nv_bfloat16* dl){
#pragma unroll
    for(int g=0; g<8; g++){
        float4 a=((const float4*)s)[2*g], b=((const float4*)s)[2*g+1];
        float f[8]={a.x,a.y,a.z,a.w,b.x,b.y,b.z,b.w};
        __align__(16) __nv_bfloat16 h[8], l[8];
#pragma unroll
        for(int i=0;i<8;i++){ h[i]=__float2bfloat16_rn(f[i]); l[i]=__float2bfloat16_rn(f[i]-__bfloat162float(h[i])); }
        ((uint4*)dh)[g]=*(const uint4*)h; ((uint4*)dl)[g]=*(const uint4*)l;
    }
}

// ============== K0: pre-convert W to bf16 hi/lo =============================
__global__ void k0(const float* __restrict__ Wq, const float* __restrict__ Wk,
                   const float* __restrict__ Wv){
    const float* W = blockIdx.x==0?Wq:(blockIdx.x==1?Wk:Wv);
    int h = threadIdx.x;
    size_t o = (size_t)blockIdx.x*16384 + (size_t)h*128;
    cvt64(W + (size_t)h*128,      g_w_hi+o,    g_w_lo+o);
    cvt64(W + (size_t)h*128 + 64, g_w_hi+o+64, g_w_lo+o+64);
}

// ============== K1: qkv projection, fused m-loop, cp.async W ================
#define K1_B0 69632
#define K1_B1 139264
#define K1_BIAS 208896
#define SM1 210432

__device__ __forceinline__ void prefetch_w(unsigned sbuf, int m, int tid){
#pragma unroll
    for(int i=0;i<16;i++){
        int c = tid + 256*i;
        int op = c>>11, e = c&2047, row = e>>4, col8 = e&15;
        const __nv_bfloat16* s = (op? g_w_lo : g_w_hi) + (size_t)m*16384 + row*128 + col8*8;
        cpa(sbuf + (unsigned)op*34816u + (unsigned)(row*272 + col8*16), s);
    }
}

__global__ __launch_bounds__(256,1) void k1(const float* __restrict__ x,
    const float* __restrict__ bq, const float* __restrict__ bk, const float* __restrict__ bv)
{
    extern __shared__ char sm[];
    unsigned sb = smem_u32(sm);
    const int tid=threadIdx.x, lane=tid&31, warp=tid>>5, wr=warp>>1, wc=warp&1;
    const int r0=blockIdx.x*128;
    __nv_bfloat16* Ah=(__nv_bfloat16*)(sm); __nv_bfloat16* Al=(__nv_bfloat16*)(sm+34816);
    float* bias_s=(float*)(sm+K1_BIAS);
    prefetch_w(sb+K1_B0, 0, tid); CPC();
    const int r=tid>>1, hf=tid&1;
    cvt64(x + (size_t)(r0+r)*128 + hf*64, Ah + r*LDBE + hf*64, Al + r*LDBE + hf*64);
    if(tid<128){ bias_s[tid]=bq[tid]; bias_s[128+tid]=bk[tid]; bias_s[256+tid]=bv[tid]; }
    for(int m=0;m<3;m++){
        unsigned bcur = (m&1)? K1_B1 : K1_B0;
        unsigned both = (m&1)? K1_B0 : K1_B1;
        CPW(0); __syncthreads();
        if(m<2){ prefetch_w(sb+both, m+1, tid); CPC(); }
        float acc[2][8][4]; zacc(acc);
        warp_pass<272,8>(sb+0,     sb+bcur,       acc, wr, wc, lane);
        warp_pass<272,8>(sb+0,     sb+bcur+34816, acc, wr, wc, lane);
        warp_pass<272,8>(sb+34816, sb+bcur,       acc, wr, wc, lane);
        __syncthreads();
        float* stag=(float*)(sm+bcur);
        stage_acc(stag, acc, wr, wc, lane);
        __syncthreads();
        if(m==0){
#pragma unroll
            for(int g=0; g<8; g++){
                __align__(16) __nv_bfloat16 h[8], l[8];
#pragma unroll
                for(int i=0;i<8;i++){
                    float v = stag[r*LDS + hf*64 + g*8 + i] + bias_s[hf*64+g*8+i];
                    h[i]=__float2bfloat16_rn(v); l[i]=__float2bfloat16_rn(v-__bfloat162float(h[i]));
                }
                size_t off=(size_t)(r0+r)*128 + hf*64 + g*8;
                *(uint4*)(g_q_hi+off)=*(const uint4*)h; *(uint4*)(g_q_lo+off)=*(const uint4*)l;
            }
        } else {
            const int h_=r, tp=hf, bb=r0>>13, tl0=r0&8191;
            const float bsv=bias_s[m*128 + h_];
            __nv_bfloat16* dh=(m==1?g_k_hi:g_v_hi)+(size_t)(bb*128+h_)*S_LEN+tl0+tp*64;
            __nv_bfloat16* dl=(m==1?g_k_lo:g_v_lo)+(size_t)(bb*128+h_)*S_LEN+tl0+tp*64;
#pragma unroll
            for(int tg=0; tg<8; tg++){
                __align__(16) __nv_bfloat16 h[8], l[8];
#pragma unroll
                for(int i=0;i<8;i++){
                    float v = stag[(tp*64+tg*8+i)*LDS + h_] + bsv;
                    h[i]=__float2bfloat16_rn(v); l[i]=__float2bfloat16_rn(v-__bfloat162float(h[i]));
                }
                *(uint4*)(dh+tg*8)=*(const uint4*)h; *(uint4*)(dl+tg*8)=*(const uint4*)l;
            }
        }
    }
}

// ============== K2: C'_m = sum_t v (x) k, 4 pipelined 64-t quarters =========
#define K2_BUFSZ 73728          // vh,vl,kh,kl each 128*144
#define SM2 147456

__device__ __forceinline__ void prefetch_kv(unsigned sbuf, int b, int t0, int tid){
#pragma unroll
    for(int i=0;i<16;i++){
        int c = tid + 256*i;
        int op = c>>10, e=c&1023, row=e>>3, col8=e&7;
        const __nv_bfloat16* base = (op==0)? g_v_hi : (op==1)? g_v_lo : (op==2)? g_k_hi : g_k_lo;
        cpa(sbuf + (unsigned)op*18432u + (unsigned)(row*144 + col8*16),
            base + (size_t)(b*128+row)*S_LEN + t0 + col8*8);
    }
}

__global__ __launch_bounds__(256,1) void k2()
{
    extern __shared__ char sm[];
    unsigned sb=smem_u32(sm);
    const int tid=threadIdx.x, lane=tid&31, warp=tid>>5, wr=warp>>1, wc=warp&1;
    const int bm=blockIdx.x, b=bm>>5, mc=bm&31;
    prefetch_kv(sb, b, mc*256, tid); CPC();
    float acc[2][8][4]; zacc(acc);
    for(int qt=0; qt<4; qt++){
        unsigned buf = (qt&1)? K2_BUFSZ : 0u;
        if(qt<3){ prefetch_kv(sb + ((qt&1)?0u:K2_BUFSZ), b, mc*256+(qt+1)*64, tid); CPC(); CPW(1); }
        else CPW(0);
        __syncthreads();
        warp_pass<144,4>(sb+buf+0,     sb+buf+36864, acc, wr, wc, lane);
        warp_pass<144,4>(sb+buf+0,     sb+buf+55296, acc, wr, wc, lane);
        warp_pass<144,4>(sb+buf+18432, sb+buf+36864, acc, wr, wc, lane);
        __syncthreads();
    }
    float* stag=(float*)sm;
    stage_acc(stag, acc, wr, wc, lane);
    __syncthreads();
    const int r=tid>>1, hf=tid&1;
    float* dst=g_C+(size_t)(bm*128+r)*128+hf*64;
#pragma unroll
    for(int g=0; g<16; g++){
        float4 o=make_float4(stag[r*LDS+hf*64+g*4],stag[r*LDS+hf*64+g*4+1],
                             stag[r*LDS+hf*64+g*4+2],stag[r*LDS+hf*64+g*4+3]);
        ((float4*)dst)[g]=o;
    }
}

// ============== K3: out = scale*(q @ Csum^T - edges), 2 halves per CTA ======
#define K3_BH 69632
#define K3_BL 104448
#define K3_EXT 139264
#define SM3 142336

__device__ __forceinline__ void prefetch_q(unsigned sA, size_t qrow0, int tid){
#pragma unroll
    for(int i=0;i<16;i++){
        int c = tid + 256*i;
        int op = c>>11, e=c&2047, row=e>>4, col8=e&15;
        const __nv_bfloat16* base = op? g_q_lo : g_q_hi;
        cpa(sA + (unsigned)op*34816u + (unsigned)(row*272 + col8*16),
            base + (qrow0+row)*128 + col8*8);
    }
}

__global__ __launch_bounds__(256,1) void k3(float* __restrict__ out)
{
    extern __shared__ char sm[];
    unsigned sb=smem_u32(sm);
    const int tid=threadIdx.x, lane=tid&31, warp=tid>>5, wr=warp>>1, wc=warp&1;
    const int idx=blockIdx.x, b=idx>>5, n=idx&31;
    __nv_bfloat16* Ah=(__nv_bfloat16*)(sm); __nv_bfloat16* Al=(__nv_bfloat16*)(sm+34816);
    __nv_bfloat16* Bh=(__nv_bfloat16*)(sm+K3_BH); __nv_bfloat16* Bl=(__nv_bfloat16*)(sm+K3_BL);
    float* keL=(float*)(sm+K3_EXT);      float* veL=(float*)(sm+K3_EXT+512);
    float* keR=(float*)(sm+K3_EXT+1024); float* veR=(float*)(sm+K3_EXT+1536);
    float* dls=(float*)(sm+K3_EXT+2048); float* drs=(float*)(sm+K3_EXT+2560);
    const int r=tid>>1, hf=tid&1;
    const size_t qbase=(size_t)b*S_LEN + n*256;
    prefetch_q(sb, qbase, tid); CPC();
    { // B rows = Csum[ho=r][hk], summed over valid chunks, cvt to hi/lo
        const int mlo=(n>0)?n-1:0, mhi=(n<31)?n+1:31;
        float s[64];
#pragma unroll
        for(int j=0;j<64;j++) s[j]=0.f;
        for(int mm=mlo; mm<=mhi; mm++){
            const float4* p=(const float4*)(g_C+(size_t)((b*32+mm)*128+r)*128+hf*64);
#pragma unroll
            for(int g=0; g<16; g++){ float4 v=p[g]; s[g*4]+=v.x; s[g*4+1]+=v.y; s[g*4+2]+=v.z; s[g*4+3]+=v.w; }
        }
        cvt64(s, Bh+r*LDBE+hf*64, Bl+r*LDBE+hf*64);
    }
    if(tid<128){
        int teL=n*256-256, teR=n*256+511;
        size_t rb=(size_t)(b*128+tid)*S_LEN;
        keL[tid]=(n>0)? __bfloat162float(g_k_hi[rb+teL])+__bfloat162float(g_k_lo[rb+teL]):0.f;
        veL[tid]=(n>0)? __bfloat162float(g_v_hi[rb+teL])+__bfloat162float(g_v_lo[rb+teL]):0.f;
        keR[tid]=(n<31)? __bfloat162float(g_k_hi[rb+teR])+__bfloat162float(g_k_lo[rb+teR]):0.f;
        veR[tid]=(n<31)? __bfloat162float(g_v_hi[rb+teR])+__bfloat162float(g_v_lo[rb+teR]):0.f;
    }
    const float scale=0.08838834764831845f;
    for(int half=0; half<2; half++){
        CPW(0); __syncthreads();
        if(tid<128){
            float dl=0.f, dr=0.f;
#pragma unroll 16
            for(int c=0; c<128; c++){
                float q=__bfloat162float(Ah[tid*LDBE+c])+__bfloat162float(Al[tid*LDBE+c]);
                dl+=q*keL[c]; dr+=q*keR[c];
            }
            dls[tid]=dl; drs[tid]=dr;
        }
        float acc[2][8][4]; zacc(acc);
        warp_pass<272,8>(sb+0,     sb+K3_BH, acc, wr, wc, lane);
        warp_pass<272,8>(sb+0,     sb+K3_BL, acc, wr, wc, lane);
        warp_pass<272,8>(sb+34816, sb+K3_BH, acc, wr, wc, lane);
        __syncthreads();
        float* stag=(float*)sm;
        stage_acc(stag, acc, wr, wc, lane);
        __syncthreads();
        const float dlv=dls[r], drv=drs[r];
        float* op=out+(qbase+half*128+r)*128+hf*64;
#pragma unroll
        for(int g=0; g<16; g++){
            int c0=hf*64+g*4;
            float4 o;
            o.x=scale*(stag[r*LDS+c0+0]-dlv*veL[c0+0]-drv*veR[c0+0]);
            o.y=scale*(stag[r*LDS+c0+1]-dlv*veL[c0+1]-drv*veR[c0+1]);
            o.z=scale*(stag[r*LDS+c0+2]-dlv*veL[c0+2]-drv*veR[c0+2]);
            o.w=scale*(stag[r*LDS+c0+3]-dlv*veL[c0+3]-drv*veR[c0+3]);
            ((float4*)op)[g]=o;
        }
        if(half==0){
            __syncthreads();
            prefetch_q(sb, qbase+128, tid); CPC();
        }
    }
}

// ---------------------------------------------------------------------------
extern "C" void kernel_launch(void* const* d_in, const int* in_sizes, int n_in,
                              void* d_out, int out_size)
{
    const float* x =(const float*)d_in[0];
    const float* Wq=(const float*)d_in[1]; const float* bq=(const float*)d_in[2];
    const float* Wk=(const float*)d_in[3]; const float* bk=(const float*)d_in[4];
    const float* Wv=(const float*)d_in[5]; const float* bv=(const float*)d_in[6];
    float* out=(float*)d_out;
    cudaFuncSetAttribute(k1, cudaFuncAttributeMaxDynamicSharedMemorySize, SM1);
    cudaFuncSetAttribute(k2, cudaFuncAttributeMaxDynamicSharedMemorySize, SM2);
    cudaFuncSetAttribute(k3, cudaFuncAttributeMaxDynamicSharedMemorySize, SM3);
    k0<<<3,128>>>(Wq,Wk,Wv);
    k1<<<NROWS/128,256,SM1>>>(x,bq,bk,bv);
    k2<<<NBATCH*NB,256,SM2>>>();
    k3<<<NBATCH*NB,256,SM3>>>(out);
}